// round 11
// baseline (speedup 1.0000x reference)
#include <cuda_runtime.h>

// HEALPixPadding: [8*12, 256, 64, 64] fp32, p=2 -> [96, 256, 68, 68]
// One block per (batch, channel, face), face innermost. Output plane written
// as 1156 aligned float4s (960 interior quads + 196 table-driven border quads)
// -> every store is a full, aligned STG.128; plane coverage is contiguous.

constexpr int NB4        = 196;      // border float4s per face
constexpr int PLANE_OUT  = 4624;     // 68*68
constexpr int PLANE_OUT4 = 1156;     // float4s per plane

// per border-quad: sources for the 4 cells (offsets within (b,ch) input group)
__device__ uint4 btab_src[12 * NB4];
// .x = dst float4 index within out group; .y = blend: src(24b)|pos<<28|1<<31
__device__ uint2 btab_meta[12 * NB4];

// cell -> (primary src, optional blend src) within (b,ch) input group.
// encoding: face*2^20 + r*64 + c
__device__ void cellmap(int f, int r, int c, int& s0, int& s1)
{
    int typ = f >> 2, n = f & 3;
    int ft, ftl, flf, fbl, fbo, fbr, frg, ftr;
    if (typ == 0) {
        ft  = (n + 1) & 3;  ftl = (n + 2) & 3;  flf = (n + 3) & 3;  fbl = flf;
        fbo = n + 4;        fbr = n + 8;        frg = ((n + 1) & 3) + 4;  ftr = ft;
    } else if (typ == 1) {
        ft  = n;            flf = (n + 3) & 3;  fbl = ((n + 3) & 3) + 4;
        fbo = ((n + 3) & 3) + 8;  frg = n + 8;  ftr = ((n + 1) & 3) + 4;
        ftl = -1; fbr = -1;
    } else {
        ft  = ((n + 1) & 3) + 4;  ftl = n;  flf = n + 4;
        fbl = ((n + 3) & 3) + 8;  fbo = fbl;
        fbr = ((n + 2) & 3) + 8;  frg = ((n + 1) & 3) + 8;  ftr = frg;
    }

    int rg_r = (r < 2) ? 0 : (r < 66 ? 1 : 2);
    int rg_c = (c < 2) ? 0 : (c < 66 ? 1 : 2);
    int reg  = rg_r * 3 + rg_c;

    int sf0 = 0, sr0 = 0, sc0 = 0;
    int sf1 = -1, sr1 = 0, sc1 = 0;

    switch (reg) {
    case 0:
        if (typ == 0)      { sf0 = ftl; sr0 = 1 - r;   sc0 = 1 - c; }
        else if (typ == 2) { sf0 = ftl; sr0 = 62 + r;  sc0 = 62 + c; }
        else {
            if (c > r)      { sf0 = ft;  sr0 = 62 + r;     sc0 = c - r - 1; }
            else if (c < r) { sf0 = flf; sr0 = r - c - 1;  sc0 = 62 + c; }
            else            { sf0 = ft;  sr0 = 62 + r;  sc0 = 0;
                              sf1 = flf; sr1 = 0;       sc1 = 62 + r; }
        }
        break;
    case 1:
        if (typ == 0) { sf0 = ft; sr0 = c - 2;  sc0 = 1 - r; }
        else          { sf0 = ft; sr0 = 62 + r; sc0 = c - 2; }
        break;
    case 2:
        sf0 = ftr; sr0 = 62 + r; sc0 = c - 66;
        break;
    case 3:
        if (typ == 0) { sf0 = flf; sr0 = 1 - c;  sc0 = r - 2; }
        else          { sf0 = flf; sr0 = r - 2;  sc0 = 62 + c; }
        break;
    case 5:
        if (typ == 2) { sf0 = frg; sr0 = 129 - c; sc0 = r - 2; }
        else          { sf0 = frg; sr0 = r - 2;   sc0 = c - 66; }
        break;
    case 6:
        sf0 = fbl; sr0 = r - 66; sc0 = 62 + c;
        break;
    case 7:
        if (typ == 2) { sf0 = fbo; sr0 = c - 2;  sc0 = 129 - r; }
        else          { sf0 = fbo; sr0 = r - 66; sc0 = c - 2; }
        break;
    default:
        if (typ == 0)      { sf0 = fbr; sr0 = r - 66;  sc0 = c - 66; }
        else if (typ == 2) { sf0 = fbr; sr0 = 129 - r; sc0 = 129 - c; }
        else {
            int rr = r - 66, cc = c - 66;
            if (cc < rr)      { sf0 = fbo; sr0 = rr;            sc0 = 64 - rr + cc; }
            else if (cc > rr) { sf0 = frg; sr0 = 64 - cc + rr;  sc0 = cc; }
            else              { sf0 = fbo; sr0 = rr; sc0 = 63;
                                sf1 = frg; sr1 = 63; sc1 = rr; }
        }
        break;
    }

    s0 = (sf0 << 20) + sr0 * 64 + sc0;
    s1 = (sf1 >= 0) ? ((sf1 << 20) + sr1 * 64 + sc1) : -1;
}

__global__ void __launch_bounds__(256) hpx_build_tab()
{
    int j = blockIdx.x * 256 + threadIdx.x;
    if (j >= 12 * NB4) return;

    int f = j / NB4;
    int p = j - f * NB4;

    // p -> (row r, quad q): rows 0,1 all quads; rows 66,67 all quads;
    // rows 2..65 quads 0 and 16.
    int r, q;
    if (p < 34)      { r = p / 17;              q = p % 17; }
    else if (p < 68) { int m = p - 34; r = 66 + m / 17; q = m % 17; }
    else             { int m = p - 68; r = 2 + (m >> 1); q = (m & 1) * 16; }

    unsigned src[4];
    unsigned blend = 0;
    int c0 = q * 4;
    #pragma unroll
    for (int u = 0; u < 4; u++) {
        int c = c0 + u;
        if (r >= 2 && r < 66 && c >= 2 && c < 66) {
            src[u] = (unsigned)((f << 20) + (r - 2) * 64 + (c - 2));
        } else {
            int s0, s1;
            cellmap(f, r, c, s0, s1);
            src[u] = (unsigned)s0;
            if (s1 >= 0)
                blend = 0x80000000u | ((unsigned)u << 28) | (unsigned)s1;
        }
    }

    btab_src[j]  = make_uint4(src[0], src[1], src[2], src[3]);
    btab_meta[j] = make_uint2((unsigned)(f * 256 * PLANE_OUT4 + r * 17 + q), blend);
}

__global__ void __launch_bounds__(256) hpx_pad_face(const float* __restrict__ in,
                                                    float* __restrict__ out)
{
    const unsigned tid = threadIdx.x;
    const unsigned blk = blockIdx.x;            // bb*3072 + ch*12 + f
    const unsigned bb  = blk / 3072u;
    const unsigned rem = blk - bb * 3072u;
    const unsigned ch  = rem / 12u;
    const unsigned f   = rem - ch * 12u;

    const float*  inGroup = in + ((size_t)bb * 3072u + ch) * 4096u;
    float4*       outG4   = reinterpret_cast<float4*>(
                              out + ((size_t)bb * 3072u + ch) * (size_t)PLANE_OUT);
    const float2* in2     = reinterpret_cast<const float2*>(
                              inGroup + (size_t)f * 1048576u);   // 256*4096
    const unsigned o4base = f * 256u * (unsigned)PLANE_OUT4;

    // ---- border quad: table + gathers issued first (latency hides) ----
    const bool bord = tid < (unsigned)NB4;
    float v0, v1, v2, v3;
    uint2 m = make_uint2(0u, 0u);
    if (bord) {
        uint4 s = __ldg(&btab_src[f * NB4 + tid]);
        m = __ldg(&btab_meta[f * NB4 + tid]);
        v0 = __ldg(inGroup + s.x);
        v1 = __ldg(inGroup + s.y);
        v2 = __ldg(inGroup + s.z);
        v3 = __ldg(inGroup + s.w);
        if (m.y) {
            float vb = 0.5f * __ldg(inGroup + (m.y & 0x00FFFFFFu));
            unsigned pos = (m.y >> 28) & 3u;
            if (pos == 0u)      v0 = 0.5f * v0 + vb;
            else if (pos == 1u) v1 = 0.5f * v1 + vb;
            else if (pos == 2u) v2 = 0.5f * v2 + vb;
            else                v3 = 0.5f * v3 + vb;
        }
    }

    // ---- interior: 960 aligned float4 stores per face ----
    #pragma unroll
    for (int k = 0; k < 4; k++) {
        unsigned i = tid + (unsigned)k * 256u;
        if (k == 3 && i >= 960u) break;          // tid >= 192 done
        unsigned r2 = i / 15u;                   // 0..63
        unsigned cc = i - r2 * 15u;              // 0..14
        unsigned s2 = r2 * 32u + 2u * cc + 1u;   // float2 index (aligned)
        float2 a = in2[s2];
        float2 b = in2[s2 + 1u];
        unsigned dst = o4base + (r2 + 2u) * 17u + cc + 1u;
        __stcs(&outG4[dst], make_float4(a.x, a.y, b.x, b.y));
    }

    // ---- border store: aligned STG.128 ----
    if (bord)
        __stcs(&outG4[m.x], make_float4(v0, v1, v2, v3));
}

extern "C" void kernel_launch(void* const* d_in, const int* in_sizes, int n_in,
                              void* d_out, int out_size)
{
    const float* in = (const float*)d_in[0];
    float* out = (float*)d_out;
    hpx_build_tab<<<(12 * NB4 + 255) / 256, 256>>>();
    hpx_pad_face<<<24576, 256>>>(in, out);
}

// round 12
// speedup vs baseline: 1.0273x; 1.0273x over previous
#include <cuda_runtime.h>

// HEALPixPadding: [8*12, 256, 64, 64] fp32, p=2 -> [96, 256, 68, 68]
// One block per (batch, channel, face), face innermost. Interior: warp does
// 2 rows/iter, aligned LDG.128 + shfl_up realignment + aligned STG.128.
// Border: 196 table-driven aligned float4 quads per face.

constexpr int NB4        = 196;      // border float4s per face
constexpr int PLANE_OUT  = 4624;     // 68*68
constexpr int PLANE_OUT4 = 1156;     // float4s per plane

__device__ uint4 btab_src[12 * NB4];
__device__ uint2 btab_meta[12 * NB4];  // .x dst quad idx, .y blend src|pos<<28|1<<31

// cell -> (primary src, optional blend src) within (b,ch) input group.
// encoding: face*2^20 + r*64 + c
__device__ void cellmap(int f, int r, int c, int& s0, int& s1)
{
    int typ = f >> 2, n = f & 3;
    int ft, ftl, flf, fbl, fbo, fbr, frg, ftr;
    if (typ == 0) {
        ft  = (n + 1) & 3;  ftl = (n + 2) & 3;  flf = (n + 3) & 3;  fbl = flf;
        fbo = n + 4;        fbr = n + 8;        frg = ((n + 1) & 3) + 4;  ftr = ft;
    } else if (typ == 1) {
        ft  = n;            flf = (n + 3) & 3;  fbl = ((n + 3) & 3) + 4;
        fbo = ((n + 3) & 3) + 8;  frg = n + 8;  ftr = ((n + 1) & 3) + 4;
        ftl = -1; fbr = -1;
    } else {
        ft  = ((n + 1) & 3) + 4;  ftl = n;  flf = n + 4;
        fbl = ((n + 3) & 3) + 8;  fbo = fbl;
        fbr = ((n + 2) & 3) + 8;  frg = ((n + 1) & 3) + 8;  ftr = frg;
    }

    int rg_r = (r < 2) ? 0 : (r < 66 ? 1 : 2);
    int rg_c = (c < 2) ? 0 : (c < 66 ? 1 : 2);
    int reg  = rg_r * 3 + rg_c;

    int sf0 = 0, sr0 = 0, sc0 = 0;
    int sf1 = -1, sr1 = 0, sc1 = 0;

    switch (reg) {
    case 0:
        if (typ == 0)      { sf0 = ftl; sr0 = 1 - r;   sc0 = 1 - c; }
        else if (typ == 2) { sf0 = ftl; sr0 = 62 + r;  sc0 = 62 + c; }
        else {
            if (c > r)      { sf0 = ft;  sr0 = 62 + r;     sc0 = c - r - 1; }
            else if (c < r) { sf0 = flf; sr0 = r - c - 1;  sc0 = 62 + c; }
            else            { sf0 = ft;  sr0 = 62 + r;  sc0 = 0;
                              sf1 = flf; sr1 = 0;       sc1 = 62 + r; }
        }
        break;
    case 1:
        if (typ == 0) { sf0 = ft; sr0 = c - 2;  sc0 = 1 - r; }
        else          { sf0 = ft; sr0 = 62 + r; sc0 = c - 2; }
        break;
    case 2:
        sf0 = ftr; sr0 = 62 + r; sc0 = c - 66;
        break;
    case 3:
        if (typ == 0) { sf0 = flf; sr0 = 1 - c;  sc0 = r - 2; }
        else          { sf0 = flf; sr0 = r - 2;  sc0 = 62 + c; }
        break;
    case 5:
        if (typ == 2) { sf0 = frg; sr0 = 129 - c; sc0 = r - 2; }
        else          { sf0 = frg; sr0 = r - 2;   sc0 = c - 66; }
        break;
    case 6:
        sf0 = fbl; sr0 = r - 66; sc0 = 62 + c;
        break;
    case 7:
        if (typ == 2) { sf0 = fbo; sr0 = c - 2;  sc0 = 129 - r; }
        else          { sf0 = fbo; sr0 = r - 66; sc0 = c - 2; }
        break;
    default:
        if (typ == 0)      { sf0 = fbr; sr0 = r - 66;  sc0 = c - 66; }
        else if (typ == 2) { sf0 = fbr; sr0 = 129 - r; sc0 = 129 - c; }
        else {
            int rr = r - 66, cc = c - 66;
            if (cc < rr)      { sf0 = fbo; sr0 = rr;            sc0 = 64 - rr + cc; }
            else if (cc > rr) { sf0 = frg; sr0 = 64 - cc + rr;  sc0 = cc; }
            else              { sf0 = fbo; sr0 = rr; sc0 = 63;
                                sf1 = frg; sr1 = 63; sc1 = rr; }
        }
        break;
    }

    s0 = (sf0 << 20) + sr0 * 64 + sc0;
    s1 = (sf1 >= 0) ? ((sf1 << 20) + sr1 * 64 + sc1) : -1;
}

__global__ void __launch_bounds__(256) hpx_build_tab()
{
    int j = blockIdx.x * 256 + threadIdx.x;
    if (j >= 12 * NB4) return;

    int f = j / NB4;
    int p = j - f * NB4;

    // p -> (row r, quad q): rows 0,1,66,67 all 17 quads; rows 2..65 quads 0,16.
    int r, q;
    if (p < 34)      { r = p / 17;              q = p % 17; }
    else if (p < 68) { int m = p - 34; r = 66 + m / 17; q = m % 17; }
    else             { int m = p - 68; r = 2 + (m >> 1); q = (m & 1) * 16; }

    unsigned src[4];
    unsigned blend = 0;
    int c0 = q * 4;
    #pragma unroll
    for (int u = 0; u < 4; u++) {
        int c = c0 + u;
        if (r >= 2 && r < 66 && c >= 2 && c < 66) {
            src[u] = (unsigned)((f << 20) + (r - 2) * 64 + (c - 2));
        } else {
            int s0, s1;
            cellmap(f, r, c, s0, s1);
            src[u] = (unsigned)s0;
            if (s1 >= 0)
                blend = 0x80000000u | ((unsigned)u << 28) | (unsigned)s1;
        }
    }

    btab_src[j]  = make_uint4(src[0], src[1], src[2], src[3]);
    btab_meta[j] = make_uint2((unsigned)(f * 256 * PLANE_OUT4 + r * 17 + q), blend);
}

__global__ void __launch_bounds__(256) hpx_pad_face(const float* __restrict__ in,
                                                    float* __restrict__ out)
{
    const unsigned tid  = threadIdx.x;
    const unsigned lane = tid & 31u;
    const unsigned warp = tid >> 5;
    const unsigned half = lane >> 4;      // 0 = row A, 1 = row B
    const unsigned j    = lane & 15u;     // input quad within row

    const unsigned blk = blockIdx.x;      // bb*3072 + ch*12 + f
    const unsigned bb  = blk / 3072u;
    const unsigned rem = blk - bb * 3072u;
    const unsigned ch  = rem / 12u;
    const unsigned f   = rem - ch * 12u;

    const float*  inGroup = in + ((size_t)bb * 3072u + ch) * 4096u;
    float4*       outG4   = reinterpret_cast<float4*>(
                              out + ((size_t)bb * 3072u + ch) * (size_t)PLANE_OUT);
    const float4* in4     = reinterpret_cast<const float4*>(
                              inGroup + (size_t)f * 1048576u);   // 256*4096
    const unsigned o4base = f * 256u * (unsigned)PLANE_OUT4;

    // ---- border quad: table + gathers issued first (latency hides) ----
    const bool bord = tid < (unsigned)NB4;
    float v0, v1, v2, v3;
    uint2 m = make_uint2(0u, 0u);
    if (bord) {
        uint4 s = __ldg(&btab_src[f * NB4 + tid]);
        m = __ldg(&btab_meta[f * NB4 + tid]);
        v0 = __ldg(inGroup + s.x);
        v1 = __ldg(inGroup + s.y);
        v2 = __ldg(inGroup + s.z);
        v3 = __ldg(inGroup + s.w);
        if (m.y) {
            float vb = 0.5f * __ldg(inGroup + (m.y & 0x00FFFFFFu));
            unsigned pos = (m.y >> 28) & 3u;
            if (pos == 0u)      v0 = 0.5f * v0 + vb;
            else if (pos == 1u) v1 = 0.5f * v1 + vb;
            else if (pos == 2u) v2 = 0.5f * v2 + vb;
            else                v3 = 0.5f * v3 + vb;
        }
    }

    // ---- interior: warp = 2 rows, aligned LDG.128 -> shfl -> aligned STG.128 ----
    #pragma unroll
    for (unsigned k = 0; k < 4u; k++) {
        unsigned row = warp * 8u + 2u * k + half;        // 0..63
        float4 v = in4[row * 16u + j];
        float pz = __shfl_up_sync(0xFFFFFFFFu, v.z, 1);
        float pw = __shfl_up_sync(0xFFFFFFFFu, v.w, 1);
        if (j)   // output quads 1..15 (0 and 16 are border quads)
            __stcs(&outG4[o4base + (row + 2u) * 17u + j],
                   make_float4(pz, pw, v.x, v.y));
    }

    // ---- border store: aligned STG.128 ----
    if (bord)
        __stcs(&outG4[m.x], make_float4(v0, v1, v2, v3));
}

extern "C" void kernel_launch(void* const* d_in, const int* in_sizes, int n_in,
                              void* d_out, int out_size)
{
    const float* in = (const float*)d_in[0];
    float* out = (float*)d_out;
    hpx_build_tab<<<(12 * NB4 + 255) / 256, 256>>>();
    hpx_pad_face<<<24576, 256>>>(in, out);
}

// round 13
// speedup vs baseline: 1.0622x; 1.0340x over previous
#include <cuda_runtime.h>

// HEALPixPadding: [8*12, 256, 64, 64] fp32, p=2 -> [96, 256, 68, 68]
// One block per (batch, channel, face), face innermost. Interior: warp does
// 2 rows/iter; 4 iterations' LDG.128s front-batched (MLP=4), then shfl_up
// realignment + aligned STG.128. Border: 196 table-driven aligned quads/face.

constexpr int NB4        = 196;      // border float4s per face
constexpr int PLANE_OUT  = 4624;     // 68*68
constexpr int PLANE_OUT4 = 1156;     // float4s per plane

__device__ uint4 btab_src[12 * NB4];
__device__ uint2 btab_meta[12 * NB4];  // .x dst quad idx, .y blend src|pos<<28|1<<31

// cell -> (primary src, optional blend src) within (b,ch) input group.
// encoding: face*2^20 + r*64 + c
__device__ void cellmap(int f, int r, int c, int& s0, int& s1)
{
    int typ = f >> 2, n = f & 3;
    int ft, ftl, flf, fbl, fbo, fbr, frg, ftr;
    if (typ == 0) {
        ft  = (n + 1) & 3;  ftl = (n + 2) & 3;  flf = (n + 3) & 3;  fbl = flf;
        fbo = n + 4;        fbr = n + 8;        frg = ((n + 1) & 3) + 4;  ftr = ft;
    } else if (typ == 1) {
        ft  = n;            flf = (n + 3) & 3;  fbl = ((n + 3) & 3) + 4;
        fbo = ((n + 3) & 3) + 8;  frg = n + 8;  ftr = ((n + 1) & 3) + 4;
        ftl = -1; fbr = -1;
    } else {
        ft  = ((n + 1) & 3) + 4;  ftl = n;  flf = n + 4;
        fbl = ((n + 3) & 3) + 8;  fbo = fbl;
        fbr = ((n + 2) & 3) + 8;  frg = ((n + 1) & 3) + 8;  ftr = frg;
    }

    int rg_r = (r < 2) ? 0 : (r < 66 ? 1 : 2);
    int rg_c = (c < 2) ? 0 : (c < 66 ? 1 : 2);
    int reg  = rg_r * 3 + rg_c;

    int sf0 = 0, sr0 = 0, sc0 = 0;
    int sf1 = -1, sr1 = 0, sc1 = 0;

    switch (reg) {
    case 0:
        if (typ == 0)      { sf0 = ftl; sr0 = 1 - r;   sc0 = 1 - c; }
        else if (typ == 2) { sf0 = ftl; sr0 = 62 + r;  sc0 = 62 + c; }
        else {
            if (c > r)      { sf0 = ft;  sr0 = 62 + r;     sc0 = c - r - 1; }
            else if (c < r) { sf0 = flf; sr0 = r - c - 1;  sc0 = 62 + c; }
            else            { sf0 = ft;  sr0 = 62 + r;  sc0 = 0;
                              sf1 = flf; sr1 = 0;       sc1 = 62 + r; }
        }
        break;
    case 1:
        if (typ == 0) { sf0 = ft; sr0 = c - 2;  sc0 = 1 - r; }
        else          { sf0 = ft; sr0 = 62 + r; sc0 = c - 2; }
        break;
    case 2:
        sf0 = ftr; sr0 = 62 + r; sc0 = c - 66;
        break;
    case 3:
        if (typ == 0) { sf0 = flf; sr0 = 1 - c;  sc0 = r - 2; }
        else          { sf0 = flf; sr0 = r - 2;  sc0 = 62 + c; }
        break;
    case 5:
        if (typ == 2) { sf0 = frg; sr0 = 129 - c; sc0 = r - 2; }
        else          { sf0 = frg; sr0 = r - 2;   sc0 = c - 66; }
        break;
    case 6:
        sf0 = fbl; sr0 = r - 66; sc0 = 62 + c;
        break;
    case 7:
        if (typ == 2) { sf0 = fbo; sr0 = c - 2;  sc0 = 129 - r; }
        else          { sf0 = fbo; sr0 = r - 66; sc0 = c - 2; }
        break;
    default:
        if (typ == 0)      { sf0 = fbr; sr0 = r - 66;  sc0 = c - 66; }
        else if (typ == 2) { sf0 = fbr; sr0 = 129 - r; sc0 = 129 - c; }
        else {
            int rr = r - 66, cc = c - 66;
            if (cc < rr)      { sf0 = fbo; sr0 = rr;            sc0 = 64 - rr + cc; }
            else if (cc > rr) { sf0 = frg; sr0 = 64 - cc + rr;  sc0 = cc; }
            else              { sf0 = fbo; sr0 = rr; sc0 = 63;
                                sf1 = frg; sr1 = 63; sc1 = rr; }
        }
        break;
    }

    s0 = (sf0 << 20) + sr0 * 64 + sc0;
    s1 = (sf1 >= 0) ? ((sf1 << 20) + sr1 * 64 + sc1) : -1;
}

__global__ void __launch_bounds__(256) hpx_build_tab()
{
    int j = blockIdx.x * 256 + threadIdx.x;
    if (j >= 12 * NB4) return;

    int f = j / NB4;
    int p = j - f * NB4;

    // p -> (row r, quad q): rows 0,1,66,67 all 17 quads; rows 2..65 quads 0,16.
    int r, q;
    if (p < 34)      { r = p / 17;              q = p % 17; }
    else if (p < 68) { int m = p - 34; r = 66 + m / 17; q = m % 17; }
    else             { int m = p - 68; r = 2 + (m >> 1); q = (m & 1) * 16; }

    unsigned src[4];
    unsigned blend = 0;
    int c0 = q * 4;
    #pragma unroll
    for (int u = 0; u < 4; u++) {
        int c = c0 + u;
        if (r >= 2 && r < 66 && c >= 2 && c < 66) {
            src[u] = (unsigned)((f << 20) + (r - 2) * 64 + (c - 2));
        } else {
            int s0, s1;
            cellmap(f, r, c, s0, s1);
            src[u] = (unsigned)s0;
            if (s1 >= 0)
                blend = 0x80000000u | ((unsigned)u << 28) | (unsigned)s1;
        }
    }

    btab_src[j]  = make_uint4(src[0], src[1], src[2], src[3]);
    btab_meta[j] = make_uint2((unsigned)(f * 256 * PLANE_OUT4 + r * 17 + q), blend);
}

__global__ void __launch_bounds__(256) hpx_pad_face(const float* __restrict__ in,
                                                    float* __restrict__ out)
{
    const unsigned tid  = threadIdx.x;
    const unsigned lane = tid & 31u;
    const unsigned warp = tid >> 5;
    const unsigned half = lane >> 4;      // 0 = row A, 1 = row B
    const unsigned j    = lane & 15u;     // input quad within row

    const unsigned blk = blockIdx.x;      // bb*3072 + ch*12 + f
    const unsigned bb  = blk / 3072u;
    const unsigned rem = blk - bb * 3072u;
    const unsigned ch  = rem / 12u;
    const unsigned f   = rem - ch * 12u;

    const float*  inGroup = in + ((size_t)bb * 3072u + ch) * 4096u;
    float4*       outG4   = reinterpret_cast<float4*>(
                              out + ((size_t)bb * 3072u + ch) * (size_t)PLANE_OUT);
    const float4* in4     = reinterpret_cast<const float4*>(
                              inGroup + (size_t)f * 1048576u);   // 256*4096
    const unsigned o4base = f * 256u * (unsigned)PLANE_OUT4;

    // ---- border quad: table + gathers issued first (latency hides) ----
    const bool bord = tid < (unsigned)NB4;
    float v0, v1, v2, v3;
    uint2 m = make_uint2(0u, 0u);
    unsigned bsrc = 0u;
    if (bord) {
        uint4 s = __ldg(&btab_src[f * NB4 + tid]);
        m = __ldg(&btab_meta[f * NB4 + tid]);
        v0 = __ldg(inGroup + s.x);
        v1 = __ldg(inGroup + s.y);
        v2 = __ldg(inGroup + s.z);
        v3 = __ldg(inGroup + s.w);
        if (m.y) bsrc = m.y & 0x00FFFFFFu;
    }

    // ---- interior: front-batched LDG.128 x4 (MLP=4), then shfl + STG.128 ----
    const unsigned row0 = warp * 8u + half;   // rows row0, row0+2, row0+4, row0+6
    float4 v[4];
    #pragma unroll
    for (unsigned k = 0; k < 4u; k++)
        v[k] = in4[(row0 + 2u * k) * 16u + j];

    #pragma unroll
    for (unsigned k = 0; k < 4u; k++) {
        float pz = __shfl_up_sync(0xFFFFFFFFu, v[k].z, 1);
        float pw = __shfl_up_sync(0xFFFFFFFFu, v[k].w, 1);
        if (j)   // output quads 1..15 (0 and 16 are border quads)
            __stcs(&outG4[o4base + (row0 + 2u * k + 2u) * 17u + j],
                   make_float4(pz, pw, v[k].x, v[k].y));
    }

    // ---- border: blend + aligned STG.128 ----
    if (bord) {
        if (m.y) {
            float vb = 0.5f * __ldg(inGroup + bsrc);
            unsigned pos = (m.y >> 28) & 3u;
            if (pos == 0u)      v0 = 0.5f * v0 + vb;
            else if (pos == 1u) v1 = 0.5f * v1 + vb;
            else if (pos == 2u) v2 = 0.5f * v2 + vb;
            else                v3 = 0.5f * v3 + vb;
        }
        __stcs(&outG4[m.x], make_float4(v0, v1, v2, v3));
    }
}

extern "C" void kernel_launch(void* const* d_in, const int* in_sizes, int n_in,
                              void* d_out, int out_size)
{
    const float* in = (const float*)d_in[0];
    float* out = (float*)d_out;
    hpx_build_tab<<<(12 * NB4 + 255) / 256, 256>>>();
    hpx_pad_face<<<24576, 256>>>(in, out);
}

// round 16
// speedup vs baseline: 1.0755x; 1.0125x over previous
#include <cuda_runtime.h>

// HEALPixPadding: [8*12, 256, 64, 64] fp32, p=2 -> [96, 256, 68, 68]
// One block per (batch, channel, face), face innermost. Interior: warp does
// 2 rows/iter; 4 LDG.128 front-batched (MLP=4), shfl_up realign, aligned
// STG.128. Border: 196 aligned quads/face via a COMPILE-TIME table (no
// build kernel in the graph).

constexpr int NB4        = 196;      // border float4s per face
constexpr int PLANE_OUT  = 4624;     // 68*68
constexpr int PLANE_OUT4 = 1156;     // float4s per plane
constexpr int NTAB       = 12 * NB4; // 2352

// ---------------- compile-time table construction ----------------

// cell -> (primary src, optional blend src) within (b,ch) input group.
// encoding: face*2^20 + r*64 + c
constexpr void cellmap(int f, int r, int c, int& s0, int& s1)
{
    int typ = f >> 2, n = f & 3;
    int ft = 0, ftl = 0, flf = 0, fbl = 0, fbo = 0, fbr = 0, frg = 0, ftr = 0;
    if (typ == 0) {
        ft  = (n + 1) & 3;  ftl = (n + 2) & 3;  flf = (n + 3) & 3;  fbl = flf;
        fbo = n + 4;        fbr = n + 8;        frg = ((n + 1) & 3) + 4;  ftr = ft;
    } else if (typ == 1) {
        ft  = n;            flf = (n + 3) & 3;  fbl = ((n + 3) & 3) + 4;
        fbo = ((n + 3) & 3) + 8;  frg = n + 8;  ftr = ((n + 1) & 3) + 4;
        ftl = -1; fbr = -1;
    } else {
        ft  = ((n + 1) & 3) + 4;  ftl = n;  flf = n + 4;
        fbl = ((n + 3) & 3) + 8;  fbo = fbl;
        fbr = ((n + 2) & 3) + 8;  frg = ((n + 1) & 3) + 8;  ftr = frg;
    }

    int rg_r = (r < 2) ? 0 : (r < 66 ? 1 : 2);
    int rg_c = (c < 2) ? 0 : (c < 66 ? 1 : 2);
    int reg  = rg_r * 3 + rg_c;

    int sf0 = 0, sr0 = 0, sc0 = 0;
    int sf1 = -1, sr1 = 0, sc1 = 0;

    switch (reg) {
    case 0:
        if (typ == 0)      { sf0 = ftl; sr0 = 1 - r;   sc0 = 1 - c; }
        else if (typ == 2) { sf0 = ftl; sr0 = 62 + r;  sc0 = 62 + c; }
        else {
            if (c > r)      { sf0 = ft;  sr0 = 62 + r;     sc0 = c - r - 1; }
            else if (c < r) { sf0 = flf; sr0 = r - c - 1;  sc0 = 62 + c; }
            else            { sf0 = ft;  sr0 = 62 + r;  sc0 = 0;
                              sf1 = flf; sr1 = 0;       sc1 = 62 + r; }
        }
        break;
    case 1:
        if (typ == 0) { sf0 = ft; sr0 = c - 2;  sc0 = 1 - r; }
        else          { sf0 = ft; sr0 = 62 + r; sc0 = c - 2; }
        break;
    case 2:
        sf0 = ftr; sr0 = 62 + r; sc0 = c - 66;
        break;
    case 3:
        if (typ == 0) { sf0 = flf; sr0 = 1 - c;  sc0 = r - 2; }
        else          { sf0 = flf; sr0 = r - 2;  sc0 = 62 + c; }
        break;
    case 5:
        if (typ == 2) { sf0 = frg; sr0 = 129 - c; sc0 = r - 2; }
        else          { sf0 = frg; sr0 = r - 2;   sc0 = c - 66; }
        break;
    case 6:
        sf0 = fbl; sr0 = r - 66; sc0 = 62 + c;
        break;
    case 7:
        if (typ == 2) { sf0 = fbo; sr0 = c - 2;  sc0 = 129 - r; }
        else          { sf0 = fbo; sr0 = r - 66; sc0 = c - 2; }
        break;
    default:
        if (typ == 0)      { sf0 = fbr; sr0 = r - 66;  sc0 = c - 66; }
        else if (typ == 2) { sf0 = fbr; sr0 = 129 - r; sc0 = 129 - c; }
        else {
            int rr = r - 66, cc = c - 66;
            if (cc < rr)      { sf0 = fbo; sr0 = rr;            sc0 = 64 - rr + cc; }
            else if (cc > rr) { sf0 = frg; sr0 = 64 - cc + rr;  sc0 = cc; }
            else              { sf0 = fbo; sr0 = rr; sc0 = 63;
                                sf1 = frg; sr1 = 63; sc1 = rr; }
        }
        break;
    }

    s0 = (sf0 << 20) + sr0 * 64 + sc0;
    s1 = (sf1 >= 0) ? ((sf1 << 20) + sr1 * 64 + sc1) : -1;
}

struct alignas(16) U4 { unsigned x, y, z, w; };
struct alignas(8)  U2 { unsigned x, y; };
struct TabData { U4 src[NTAB]; U2 meta[NTAB]; };

constexpr TabData build_tab()
{
    TabData t{};
    for (int f = 0; f < 12; f++) {
        for (int p = 0; p < NB4; p++) {
            int j = f * NB4 + p;

            // p -> (row r, quad q): rows 0,1,66,67 all 17 quads; rows 2..65 quads 0,16.
            int r = 0, q = 0;
            if (p < 34)      { r = p / 17;              q = p % 17; }
            else if (p < 68) { int m = p - 34; r = 66 + m / 17; q = m % 17; }
            else             { int m = p - 68; r = 2 + (m >> 1); q = (m & 1) * 16; }

            unsigned src[4] = {0, 0, 0, 0};
            unsigned blend = 0;
            int c0 = q * 4;
            for (int u = 0; u < 4; u++) {
                int c = c0 + u;
                if (r >= 2 && r < 66 && c >= 2 && c < 66) {
                    src[u] = (unsigned)((f << 20) + (r - 2) * 64 + (c - 2));
                } else {
                    int s0 = 0, s1 = -1;
                    cellmap(f, r, c, s0, s1);
                    src[u] = (unsigned)s0;
                    if (s1 >= 0)
                        blend = 0x80000000u | ((unsigned)u << 28) | (unsigned)s1;
                }
            }

            t.src[j]  = U4{src[0], src[1], src[2], src[3]};
            t.meta[j] = U2{(unsigned)(f * 256 * PLANE_OUT4 + r * 17 + q), blend};
        }
    }
    return t;
}

constexpr TabData HOST_TAB = build_tab();
__device__ const TabData g_tab = HOST_TAB;   // static init, lives in cubin .data

// ---------------- main kernel ----------------

__global__ void __launch_bounds__(256) hpx_pad_face(const float* __restrict__ in,
                                                    float* __restrict__ out)
{
    const unsigned tid  = threadIdx.x;
    const unsigned lane = tid & 31u;
    const unsigned warp = tid >> 5;
    const unsigned half = lane >> 4;      // 0 = row A, 1 = row B
    const unsigned j    = lane & 15u;     // input quad within row

    const unsigned blk = blockIdx.x;      // bb*3072 + ch*12 + f
    const unsigned bb  = blk / 3072u;
    const unsigned rem = blk - bb * 3072u;
    const unsigned ch  = rem / 12u;
    const unsigned f   = rem - ch * 12u;

    const float*  inGroup = in + ((size_t)bb * 3072u + ch) * 4096u;
    float4*       outG4   = reinterpret_cast<float4*>(
                              out + ((size_t)bb * 3072u + ch) * (size_t)PLANE_OUT);
    const float4* in4     = reinterpret_cast<const float4*>(
                              inGroup + (size_t)f * 1048576u);   // 256*4096
    const unsigned o4base = f * 256u * (unsigned)PLANE_OUT4;

    // ---- border quad: table + gathers issued first (latency hides) ----
    const bool bord = tid < (unsigned)NB4;
    float v0, v1, v2, v3;
    uint2 m = make_uint2(0u, 0u);
    unsigned bsrc = 0u;
    if (bord) {
        uint4 s = __ldg(reinterpret_cast<const uint4*>(&g_tab.src[f * NB4 + tid]));
        m = __ldg(reinterpret_cast<const uint2*>(&g_tab.meta[f * NB4 + tid]));
        v0 = __ldg(inGroup + s.x);
        v1 = __ldg(inGroup + s.y);
        v2 = __ldg(inGroup + s.z);
        v3 = __ldg(inGroup + s.w);
        if (m.y) bsrc = m.y & 0x00FFFFFFu;
    }

    // ---- interior: front-batched LDG.128 x4 (MLP=4), then shfl + STG.128 ----
    const unsigned row0 = warp * 8u + half;   // rows row0, row0+2, row0+4, row0+6
    float4 v[4];
    #pragma unroll
    for (unsigned k = 0; k < 4u; k++)
        v[k] = in4[(row0 + 2u * k) * 16u + j];

    #pragma unroll
    for (unsigned k = 0; k < 4u; k++) {
        float pz = __shfl_up_sync(0xFFFFFFFFu, v[k].z, 1);
        float pw = __shfl_up_sync(0xFFFFFFFFu, v[k].w, 1);
        if (j)   // output quads 1..15 (0 and 16 are border quads)
            __stcs(&outG4[o4base + (row0 + 2u * k + 2u) * 17u + j],
                   make_float4(pz, pw, v[k].x, v[k].y));
    }

    // ---- border: blend + aligned STG.128 ----
    if (bord) {
        if (m.y) {
            float vb = 0.5f * __ldg(inGroup + bsrc);
            unsigned pos = (m.y >> 28) & 3u;
            if (pos == 0u)      v0 = 0.5f * v0 + vb;
            else if (pos == 1u) v1 = 0.5f * v1 + vb;
            else if (pos == 2u) v2 = 0.5f * v2 + vb;
            else                v3 = 0.5f * v3 + vb;
        }
        __stcs(&outG4[m.x], make_float4(v0, v1, v2, v3));
    }
}

extern "C" void kernel_launch(void* const* d_in, const int* in_sizes, int n_in,
                              void* d_out, int out_size)
{
    const float* in = (const float*)d_in[0];
    float* out = (float*)d_out;
    hpx_pad_face<<<24576, 256>>>(in, out);
}

// round 17
// speedup vs baseline: 1.0962x; 1.0192x over previous
#include <cuda_runtime.h>

// HEALPixPadding: [8*12, 256, 64, 64] fp32, p=2 -> [96, 256, 68, 68]
// One block per (batch, channel, face), face innermost. Warp-specialized:
// warps 0-3 stream the interior (16 rows/warp, 8 LDG.128 front-batched per
// thread -> shfl_up realign -> aligned STG.128); warps 4-7 handle all 196
// border quads via a compile-time table (aligned STG.128, L2-hit gathers).

constexpr int NB4        = 196;      // border float4s per face
constexpr int PLANE_OUT  = 4624;     // 68*68
constexpr int PLANE_OUT4 = 1156;     // float4s per plane
constexpr int NTAB       = 12 * NB4; // 2352

// ---------------- compile-time table construction ----------------

// cell -> (primary src, optional blend src) within (b,ch) input group.
// encoding: face*2^20 + r*64 + c
constexpr void cellmap(int f, int r, int c, int& s0, int& s1)
{
    int typ = f >> 2, n = f & 3;
    int ft = 0, ftl = 0, flf = 0, fbl = 0, fbo = 0, fbr = 0, frg = 0, ftr = 0;
    if (typ == 0) {
        ft  = (n + 1) & 3;  ftl = (n + 2) & 3;  flf = (n + 3) & 3;  fbl = flf;
        fbo = n + 4;        fbr = n + 8;        frg = ((n + 1) & 3) + 4;  ftr = ft;
    } else if (typ == 1) {
        ft  = n;            flf = (n + 3) & 3;  fbl = ((n + 3) & 3) + 4;
        fbo = ((n + 3) & 3) + 8;  frg = n + 8;  ftr = ((n + 1) & 3) + 4;
        ftl = -1; fbr = -1;
    } else {
        ft  = ((n + 1) & 3) + 4;  ftl = n;  flf = n + 4;
        fbl = ((n + 3) & 3) + 8;  fbo = fbl;
        fbr = ((n + 2) & 3) + 8;  frg = ((n + 1) & 3) + 8;  ftr = frg;
    }

    int rg_r = (r < 2) ? 0 : (r < 66 ? 1 : 2);
    int rg_c = (c < 2) ? 0 : (c < 66 ? 1 : 2);
    int reg  = rg_r * 3 + rg_c;

    int sf0 = 0, sr0 = 0, sc0 = 0;
    int sf1 = -1, sr1 = 0, sc1 = 0;

    switch (reg) {
    case 0:
        if (typ == 0)      { sf0 = ftl; sr0 = 1 - r;   sc0 = 1 - c; }
        else if (typ == 2) { sf0 = ftl; sr0 = 62 + r;  sc0 = 62 + c; }
        else {
            if (c > r)      { sf0 = ft;  sr0 = 62 + r;     sc0 = c - r - 1; }
            else if (c < r) { sf0 = flf; sr0 = r - c - 1;  sc0 = 62 + c; }
            else            { sf0 = ft;  sr0 = 62 + r;  sc0 = 0;
                              sf1 = flf; sr1 = 0;       sc1 = 62 + r; }
        }
        break;
    case 1:
        if (typ == 0) { sf0 = ft; sr0 = c - 2;  sc0 = 1 - r; }
        else          { sf0 = ft; sr0 = 62 + r; sc0 = c - 2; }
        break;
    case 2:
        sf0 = ftr; sr0 = 62 + r; sc0 = c - 66;
        break;
    case 3:
        if (typ == 0) { sf0 = flf; sr0 = 1 - c;  sc0 = r - 2; }
        else          { sf0 = flf; sr0 = r - 2;  sc0 = 62 + c; }
        break;
    case 5:
        if (typ == 2) { sf0 = frg; sr0 = 129 - c; sc0 = r - 2; }
        else          { sf0 = frg; sr0 = r - 2;   sc0 = c - 66; }
        break;
    case 6:
        sf0 = fbl; sr0 = r - 66; sc0 = 62 + c;
        break;
    case 7:
        if (typ == 2) { sf0 = fbo; sr0 = c - 2;  sc0 = 129 - r; }
        else          { sf0 = fbo; sr0 = r - 66; sc0 = c - 2; }
        break;
    default:
        if (typ == 0)      { sf0 = fbr; sr0 = r - 66;  sc0 = c - 66; }
        else if (typ == 2) { sf0 = fbr; sr0 = 129 - r; sc0 = 129 - c; }
        else {
            int rr = r - 66, cc = c - 66;
            if (cc < rr)      { sf0 = fbo; sr0 = rr;            sc0 = 64 - rr + cc; }
            else if (cc > rr) { sf0 = frg; sr0 = 64 - cc + rr;  sc0 = cc; }
            else              { sf0 = fbo; sr0 = rr; sc0 = 63;
                                sf1 = frg; sr1 = 63; sc1 = rr; }
        }
        break;
    }

    s0 = (sf0 << 20) + sr0 * 64 + sc0;
    s1 = (sf1 >= 0) ? ((sf1 << 20) + sr1 * 64 + sc1) : -1;
}

struct alignas(16) U4 { unsigned x, y, z, w; };
struct alignas(8)  U2 { unsigned x, y; };
struct TabData { U4 src[NTAB]; U2 meta[NTAB]; };

constexpr TabData build_tab()
{
    TabData t{};
    for (int f = 0; f < 12; f++) {
        for (int p = 0; p < NB4; p++) {
            int j = f * NB4 + p;

            // p -> (row r, quad q): rows 0,1,66,67 all 17 quads; rows 2..65 quads 0,16.
            int r = 0, q = 0;
            if (p < 34)      { r = p / 17;              q = p % 17; }
            else if (p < 68) { int m = p - 34; r = 66 + m / 17; q = m % 17; }
            else             { int m = p - 68; r = 2 + (m >> 1); q = (m & 1) * 16; }

            unsigned src[4] = {0, 0, 0, 0};
            unsigned blend = 0;
            int c0 = q * 4;
            for (int u = 0; u < 4; u++) {
                int c = c0 + u;
                if (r >= 2 && r < 66 && c >= 2 && c < 66) {
                    src[u] = (unsigned)((f << 20) + (r - 2) * 64 + (c - 2));
                } else {
                    int s0 = 0, s1 = -1;
                    cellmap(f, r, c, s0, s1);
                    src[u] = (unsigned)s0;
                    if (s1 >= 0)
                        blend = 0x80000000u | ((unsigned)u << 28) | (unsigned)s1;
                }
            }

            t.src[j]  = U4{src[0], src[1], src[2], src[3]};
            t.meta[j] = U2{(unsigned)(f * 256 * PLANE_OUT4 + r * 17 + q), blend};
        }
    }
    return t;
}

constexpr TabData HOST_TAB = build_tab();
__device__ const TabData g_tab = HOST_TAB;   // static init, lives in cubin .data

// ---------------- main kernel ----------------

__global__ void __launch_bounds__(256) hpx_pad_face(const float* __restrict__ in,
                                                    float* __restrict__ out)
{
    const unsigned tid  = threadIdx.x;
    const unsigned lane = tid & 31u;

    const unsigned blk = blockIdx.x;      // bb*3072 + ch*12 + f
    const unsigned bb  = blk / 3072u;
    const unsigned rem = blk - bb * 3072u;
    const unsigned ch  = rem / 12u;
    const unsigned f   = rem - ch * 12u;

    const float*  inGroup = in + ((size_t)bb * 3072u + ch) * 4096u;
    float4*       outG4   = reinterpret_cast<float4*>(
                              out + ((size_t)bb * 3072u + ch) * (size_t)PLANE_OUT);
    const unsigned o4base = f * 256u * (unsigned)PLANE_OUT4;

    if (tid < 128u) {
        // ======== interior warps: 16 rows/warp, MLP=8 ========
        const unsigned warp = tid >> 5;           // 0..3
        const unsigned half = lane >> 4;          // 0 = even row, 1 = odd row
        const unsigned j    = lane & 15u;         // input quad within row
        const float4* in4   = reinterpret_cast<const float4*>(
                                inGroup + (size_t)f * 1048576u);   // 256*4096
        const unsigned row0 = warp * 16u + half;  // rows row0 + 2k, k=0..7

        float4 v[8];
        #pragma unroll
        for (unsigned k = 0; k < 8u; k++)
            v[k] = in4[(row0 + 2u * k) * 16u + j];

        #pragma unroll
        for (unsigned k = 0; k < 8u; k++) {
            float pz = __shfl_up_sync(0xFFFFFFFFu, v[k].z, 1);
            float pw = __shfl_up_sync(0xFFFFFFFFu, v[k].w, 1);
            if (j)   // output quads 1..15 (0 and 16 are border quads)
                __stcs(&outG4[o4base + (row0 + 2u * k + 2u) * 17u + j],
                       make_float4(pz, pw, v[k].x, v[k].y));
        }
    } else {
        // ======== border warps: all 196 table quads ========
        const unsigned e0  = tid - 128u;          // 0..127 (always valid)
        const bool     two = e0 < (unsigned)(NB4 - 128);   // e1 = e0+128 < 196

        uint4 s0 = __ldg(reinterpret_cast<const uint4*>(&g_tab.src[f * NB4 + e0]));
        uint2 m0 = __ldg(reinterpret_cast<const uint2*>(&g_tab.meta[f * NB4 + e0]));
        float a0 = __ldg(inGroup + s0.x);
        float a1 = __ldg(inGroup + s0.y);
        float a2 = __ldg(inGroup + s0.z);
        float a3 = __ldg(inGroup + s0.w);

        uint4 s1; uint2 m1 = make_uint2(0u, 0u);
        float b0, b1, b2, b3;
        if (two) {
            s1 = __ldg(reinterpret_cast<const uint4*>(&g_tab.src[f * NB4 + e0 + 128]));
            m1 = __ldg(reinterpret_cast<const uint2*>(&g_tab.meta[f * NB4 + e0 + 128]));
            b0 = __ldg(inGroup + s1.x);
            b1 = __ldg(inGroup + s1.y);
            b2 = __ldg(inGroup + s1.z);
            b3 = __ldg(inGroup + s1.w);
        }

        if (m0.y) {
            float vb = 0.5f * __ldg(inGroup + (m0.y & 0x00FFFFFFu));
            unsigned pos = (m0.y >> 28) & 3u;
            if (pos == 0u)      a0 = 0.5f * a0 + vb;
            else if (pos == 1u) a1 = 0.5f * a1 + vb;
            else if (pos == 2u) a2 = 0.5f * a2 + vb;
            else                a3 = 0.5f * a3 + vb;
        }
        __stcs(&outG4[m0.x], make_float4(a0, a1, a2, a3));

        if (two) {
            if (m1.y) {
                float vb = 0.5f * __ldg(inGroup + (m1.y & 0x00FFFFFFu));
                unsigned pos = (m1.y >> 28) & 3u;
                if (pos == 0u)      b0 = 0.5f * b0 + vb;
                else if (pos == 1u) b1 = 0.5f * b1 + vb;
                else if (pos == 2u) b2 = 0.5f * b2 + vb;
                else                b3 = 0.5f * b3 + vb;
            }
            __stcs(&outG4[m1.x], make_float4(b0, b1, b2, b3));
        }
    }
}

extern "C" void kernel_launch(void* const* d_in, const int* in_sizes, int n_in,
                              void* d_out, int out_size)
{
    const float* in = (const float*)d_in[0];
    float* out = (float*)d_out;
    hpx_pad_face<<<24576, 256>>>(in, out);
}